// round 15
// baseline (speedup 1.0000x reference)
#include <cuda_runtime.h>
#include <math.h>
#include <stdint.h>

typedef unsigned long long u64;

#define DD   256
#define BB   8
#define CHK  64
#define NC   64
#define TLEN 4096

#define SA    260
#define STB   34
#define XTILE (16*SA)
#define BT2   17408

// mma smem layout (floats)
#define OF_AL 4160
#define OF_WH 8320
#define OF_WL 17536
#define OF_RED 26752
#define SMEMK ((26752+128)*4)        // 107520 B

// ---------------- persistent state (in-place) ----------------
static __device__ float S_w1f[4][BB][DD*DD];
static __device__ float S_w2 [6][BB][DD*DD];
static __device__ float S_w1v[2][BB][DD];
static __device__ float S_wsk[2][BB][DD];

// ---------------- per-chunk scratch ----------------
static __device__ float SC_k [BB][CHK*DD];
static __device__ float SC_v [BB][CHK*DD];
static __device__ float SC_q [BB][CHK*DD];
static __device__ float SC_h2[6][BB][CHK*DD];
static __device__ float SC_g [4][BB][CHK*DD];
static __device__ float SC_pre[6][BB][CHK*DD];
static __device__ float SC_eta[BB][CHK];
static __device__ float SC_alpha[BB][CHK];
static __device__ float SC_vsum[BB][CHK];
static __device__ float SC_gs[2][BB][CHK];
static __device__ float SC_abar[BB];

// ---------------- helpers ----------------
__device__ __forceinline__ void fmaX2(u64 &d, u64 a, u64 b){
    asm("fma.rn.f32x2 %0, %1, %2, %0;" : "+l"(d) : "l"(a), "l"(b));
}
__device__ __forceinline__ u64 pk2(float lo, float hi){
    u64 r; asm("mov.b64 %0, {%1, %2};" : "=l"(r) : "f"(lo), "f"(hi)); return r;
}
__device__ __forceinline__ float2 up2(u64 v){
    float lo, hi; asm("mov.b64 {%0, %1}, %2;" : "=f"(lo), "=f"(hi) : "l"(v));
    return make_float2(lo, hi);
}
__device__ __forceinline__ float red2(u64 v){ float2 t = up2(v); return t.x + t.y; }
__device__ __forceinline__ float geluf(float z){
    return 0.5f*z*(1.0f + erff(z*0.70710678118654752f));
}
__device__ __forceinline__ float dgeluf(float z){
    float cdf = 0.5f*(1.0f + erff(z*0.70710678118654752f));
    float pdf = expf(-0.5f*z*z)*0.39894228040143267f;
    return cdf + z*pdf;
}
__device__ __forceinline__ float warp_sum(float v){
    #pragma unroll
    for(int o=16;o>0;o>>=1) v += __shfl_xor_sync(0xffffffffu, v, o);
    return v;
}
__device__ __forceinline__ float tf32hi(float f){
    uint32_t h; asm("cvt.rna.tf32.f32 %0, %1;" : "=r"(h) : "f"(f));
    return __uint_as_float(h);
}
__device__ __forceinline__ void mma8(float (&c)[4], const uint32_t (&a)[4],
                                     uint32_t b0, uint32_t b1){
    asm volatile("mma.sync.aligned.m16n8k8.row.col.f32.tf32.tf32.f32 "
        "{%0,%1,%2,%3}, {%4,%5,%6,%7}, {%8,%9}, {%0,%1,%2,%3};"
        : "+f"(c[0]),"+f"(c[1]),"+f"(c[2]),"+f"(c[3])
        : "r"(a[0]),"r"(a[1]),"r"(a[2]),"r"(a[3]), "r"(b0),"r"(b1));
}

__device__ __forceinline__ void load_tile16(float* dst, const float* __restrict__ src){
    const int tid = threadIdx.x;
    #pragma unroll
    for(int l=0;l<4;l++){
        int idx = tid + l*256;
        int r = idx>>6, qc = (idx&63)<<2;
        *reinterpret_cast<float4*>(dst + r*SA + qc) =
            *reinterpret_cast<const float4*>(src + r*DD + qc);
    }
}

// split a 16x256 activation tile from global into hi/lo smem planes (stride SA)
__device__ __forceinline__ void splitA(float* Ah, float* Al, const float* __restrict__ src){
    const int tid = threadIdx.x;
    #pragma unroll
    for(int l=0;l<4;l++){
        int idx = tid + l*256;
        int r = idx>>6, qc = (idx&63)<<2;
        float4 v = *reinterpret_cast<const float4*>(src + (size_t)r*DD + qc);
        float4 h, lo;
        h.x = tf32hi(v.x); lo.x = v.x - h.x;
        h.y = tf32hi(v.y); lo.y = v.y - h.y;
        h.z = tf32hi(v.z); lo.z = v.z - h.z;
        h.w = tf32hi(v.w); lo.w = v.w - h.w;
        *reinterpret_cast<float4*>(Ah + r*SA + qc) = h;
        *reinterpret_cast<float4*>(Al + r*SA + qc) = lo;
    }
}

// ---------------- SIMT TB GEMM (R7-proven; small paths only) ----------------
__device__ __forceinline__ void gemmTB(const float* As, const float* __restrict__ Bg,
                                       float* Bt, u64 (&acc)[4][4]){
    const int tid = threadIdx.x, tx = tid&31;
    const int rw = (tid>>5)&3, jh = tid>>7;
    const int j0 = tid>>3, qc = (tid&7)<<2;
    #pragma unroll
    for(int r=0;r<4;r++)
        #pragma unroll
        for(int j=0;j<4;j++) acc[r][j] = 0ull;

    float4 rb[8];
    #pragma unroll
    for(int l=0;l<8;l++)
        rb[l] = *reinterpret_cast<const float4*>(Bg + (size_t)(j0+32*l)*DD + qc);
    #pragma unroll
    for(int l=0;l<8;l++){
        float2* p = reinterpret_cast<float2*>(Bt + (j0+32*l)*STB + qc);
        p[0] = make_float2(rb[l].x, rb[l].y);
        p[1] = make_float2(rb[l].z, rb[l].w);
    }
    __syncthreads();

    #pragma unroll 2
    for(int p=0;p<8;p++){
        if(p<7){
            const float* src = Bg + (p+1)*32 + qc;
            #pragma unroll
            for(int l=0;l<8;l++)
                rb[l] = *reinterpret_cast<const float4*>(src + (size_t)(j0+32*l)*DD);
        }
        const float* Ar = As + rw*4*SA + p*32;
        const float* Bl = Bt + (p&1)*256*STB + (jh*128 + tx)*STB;
        #pragma unroll
        for(int c2=0;c2<16;c2++){
            u64 a0 = *reinterpret_cast<const u64*>(Ar + 0*SA + 2*c2);
            u64 a1 = *reinterpret_cast<const u64*>(Ar + 1*SA + 2*c2);
            u64 a2 = *reinterpret_cast<const u64*>(Ar + 2*SA + 2*c2);
            u64 a3 = *reinterpret_cast<const u64*>(Ar + 3*SA + 2*c2);
            #pragma unroll
            for(int jj=0;jj<4;jj++){
                u64 b = *reinterpret_cast<const u64*>(Bl + jj*32*STB + 2*c2);
                fmaX2(acc[0][jj], a0, b);
                fmaX2(acc[1][jj], a1, b);
                fmaX2(acc[2][jj], a2, b);
                fmaX2(acc[3][jj], a3, b);
            }
        }
        if(p<7){
            float* dstb = Bt + ((p+1)&1)*256*STB;
            #pragma unroll
            for(int l=0;l<8;l++){
                float2* q = reinterpret_cast<float2*>(dstb + (j0+32*l)*STB + qc);
                q[0] = make_float2(rb[l].x, rb[l].y);
                q[1] = make_float2(rb[l].z, rb[l].w);
            }
            __syncthreads();
        }
    }
}

// ---------------- tf32 mma GEMM (R13-proven) ----------------
// OUT[t,j] = sum_c A[t,c]*W[j,c] (TB=1) or sum_c A[t,c]*W[c,j] (TB=0).
// 256 thr: warp w -> cols w*32..+31 (4 n8-tiles); m16 = 16 tokens.
// Thread value map: r = g + 8*(e>>1), j = w*32 + t*8 + 2*tig + (e&1).
template<int TB>
__device__ __forceinline__ void mgemm(const float* Ah, const float* Al,
                                      const float* __restrict__ Wg,
                                      float* Wh, float* Wl, float (&acc)[4][4]){
    const int tid = threadIdx.x, tx = tid&31;
    const int w = tid>>5, g = tx>>2, tig = tx&3;
    #pragma unroll
    for(int t=0;t<4;t++)
        #pragma unroll
        for(int e=0;e<4;e++) acc[t][e] = 0.f;

    for(int p=0;p<8;p++){
        __syncthreads();
        #pragma unroll
        for(int l=0;l<8;l++){
            int idx = tid + l*256;
            float4 v;
            uint32_t o;
            if(TB){
                int j = idx>>3, qc = (idx&7)<<2;
                v = *reinterpret_cast<const float4*>(Wg + (size_t)j*DD + p*32 + qc);
                o = (uint32_t)(j*36 + qc);
            } else {
                int cc = idx>>6, qn = (idx&63)<<2;
                v = *reinterpret_cast<const float4*>(Wg + (size_t)(p*32+cc)*DD + qn);
                o = (uint32_t)(cc*264 + qn);
            }
            float4 h, lo;
            h.x = tf32hi(v.x); lo.x = v.x - h.x;
            h.y = tf32hi(v.y); lo.y = v.y - h.y;
            h.z = tf32hi(v.z); lo.z = v.z - h.z;
            h.w = tf32hi(v.w); lo.w = v.w - h.w;
            *reinterpret_cast<float4*>(Wh + o) = h;
            *reinterpret_cast<float4*>(Wl + o) = lo;
        }
        __syncthreads();
        #pragma unroll
        for(int ks=0;ks<4;ks++){
            const int kk = p*32 + ks*8;
            uint32_t ah[4], al[4];
            const float* A0 = Ah + g*SA + kk + tig;
            const float* A1 = Al + g*SA + kk + tig;
            ah[0] = __float_as_uint(A0[0]);
            ah[1] = __float_as_uint(A0[8*SA]);
            ah[2] = __float_as_uint(A0[4]);
            ah[3] = __float_as_uint(A0[8*SA+4]);
            al[0] = __float_as_uint(A1[0]);
            al[1] = __float_as_uint(A1[8*SA]);
            al[2] = __float_as_uint(A1[4]);
            al[3] = __float_as_uint(A1[8*SA+4]);
            #pragma unroll
            for(int t=0;t<4;t++){
                const int jn = w*32 + t*8 + g;
                uint32_t bh0, bh1, bl0, bl1;
                if(TB){
                    const float* P = Wh + jn*36 + ks*8 + tig;
                    const float* Q = Wl + jn*36 + ks*8 + tig;
                    bh0 = __float_as_uint(P[0]); bh1 = __float_as_uint(P[4]);
                    bl0 = __float_as_uint(Q[0]); bl1 = __float_as_uint(Q[4]);
                } else {
                    const float* P = Wh + (ks*8+tig)*264 + jn;
                    const float* Q = Wl + (ks*8+tig)*264 + jn;
                    bh0 = __float_as_uint(P[0]); bh1 = __float_as_uint(P[4*264]);
                    bl0 = __float_as_uint(Q[0]); bl1 = __float_as_uint(Q[4*264]);
                }
                mma8(acc[t], ah, bh0, bh1);
                mma8(acc[t], al, bh0, bh1);
                mma8(acc[t], ah, bl0, bl1);
            }
        }
    }
    __syncthreads();
}

// ---------------- K0 ----------------
__global__ void k0_init(const float* __restrict__ k1w, const float* __restrict__ k2w,
                        const float* __restrict__ v1w, const float* __restrict__ v2w,
                        const float* __restrict__ q1w, const float* __restrict__ q2w,
                        const float* __restrict__ e1w, const float* __restrict__ e2w,
                        const float* __restrict__ esw, const float* __restrict__ a1w,
                        const float* __restrict__ a2w, const float* __restrict__ asw,
                        const float* __restrict__ m1w, const float* __restrict__ m2w){
    const int gid = blockIdx.x*blockDim.x + threadIdx.x;
    const int m = blockIdx.y;
    if(m<4){
        const float* src = (m==0)?k1w:(m==1)?v1w:(m==2)?q1w:m1w;
        float v = src[gid];
        #pragma unroll
        for(int b=0;b<BB;b++) S_w1f[m][b][gid] = v;
    } else if(m<10){
        const int s = m-4;
        const float* src = (s==0)?k2w:(s==1)?v2w:(s==2)?q2w:(s==3)?e2w:(s==4)?a2w:m2w;
        float v = src[gid];
        #pragma unroll
        for(int b=0;b<BB;b++) S_w2[s][b][gid] = v;
    } else {
        if(gid < DD){
            #pragma unroll
            for(int b=0;b<BB;b++){
                S_w1v[0][b][gid] = e1w[gid];
                S_w1v[1][b][gid] = a1w[gid];
                S_wsk[0][b][gid] = esw[gid];
                S_wsk[1][b][gid] = asw[gid];
            }
        }
    }
}

// ---------------- K1: mma forwards k,v,q (96) + SIMT eta/alpha (32) ----------------
__global__ void __launch_bounds__(256) k1_forward(const float* __restrict__ x, int chunk){
    extern __shared__ float sm[];
    const int tid = threadIdx.x, tx = tid&31;
    const int bx = blockIdx.x;
    const int th = bx&3, gg = (bx>>2)&3, b = bx>>4;
    const int tok0 = chunk*CHK + th*16;
    const float* Xg = x + ((size_t)b*TLEN + tok0)*DD;

    if(gg < 3){
        float* Ah = sm;
        float* Al = sm + OF_AL;
        float* Wh = sm + OF_WH;
        float* Wl = sm + OF_WL;
        float* Red = sm + OF_RED;
        const int w = tid>>5, g = tx>>2, tig = tx&3;

        splitA(Ah, Al, Xg);

        float acc[4][4];
        mgemm<1>(Ah, Al, S_w2[gg][b], Wh, Wl, acc);
        #pragma unroll
        for(int t=0;t<4;t++)
            #pragma unroll
            for(int e=0;e<4;e++){
                const int r = g + ((e>>1)<<3);
                const int j = w*32 + t*8 + 2*tig + (e&1);
                float h = geluf(acc[t][e]);
                float hh = tf32hi(h);
                Ah[r*SA + j] = hh;
                Al[r*SA + j] = h - hh;
            }
        mgemm<1>(Ah, Al, S_w1f[gg][b], Wh, Wl, acc);

        float out[4][4]; float p0 = 0.f, p1 = 0.f;
        #pragma unroll
        for(int t=0;t<4;t++)
            #pragma unroll
            for(int e=0;e<4;e++){
                const int r = g + ((e>>1)<<3);
                const int j = w*32 + t*8 + 2*tig + (e&1);
                float o = Xg[(size_t)r*DD + j] + acc[t][e];
                out[t][e] = o;
                float c = (gg==1)? o : o*o;
                if(e>>1) p1 += c; else p0 += c;
            }
        p0 += __shfl_xor_sync(0xffffffffu, p0, 1);
        p0 += __shfl_xor_sync(0xffffffffu, p0, 2);
        p1 += __shfl_xor_sync(0xffffffffu, p1, 1);
        p1 += __shfl_xor_sync(0xffffffffu, p1, 2);
        if(tig==0){ Red[g*8 + w] = p0; Red[(g+8)*8 + w] = p1; }
        __syncthreads();
        float tot0 = 0.f, tot1 = 0.f;
        #pragma unroll
        for(int i=0;i<8;i++){ tot0 += Red[g*8+i]; tot1 += Red[(g+8)*8+i]; }

        if(gg==1){
            #pragma unroll
            for(int t=0;t<4;t++)
                #pragma unroll
                for(int e=0;e<4;e++){
                    const int r = g + ((e>>1)<<3);
                    const int j = w*32 + t*8 + 2*tig + (e&1);
                    SC_v[b][(th*16 + r)*DD + j] = out[t][e];
                }
            if(w==0 && tig==0){
                SC_vsum[b][th*16 + g]     = tot0;
                SC_vsum[b][th*16 + g + 8] = tot1;
            }
        } else {
            float* dst = (gg==0)? SC_k[b] : SC_q[b];
            float inv0 = 1.f / fmaxf(sqrtf(tot0), 1e-6f);
            float inv1 = 1.f / fmaxf(sqrtf(tot1), 1e-6f);
            #pragma unroll
            for(int t=0;t<4;t++)
                #pragma unroll
                for(int e=0;e<4;e++){
                    const int r = g + ((e>>1)<<3);
                    const int j = w*32 + t*8 + 2*tig + (e&1);
                    dst[(th*16 + r)*DD + j] = out[t][e] * ((e>>1)? inv1 : inv0);
                }
        }
    } else {
        const int rw = (tid>>5)&3, jh = tid>>7;
        float* Xs  = sm;
        float* Bt  = sm + XTILE;
        float* Red = sm + XTILE + BT2;
        load_tile16(Xs, Xg);

        u64 acc[4][4];
        #pragma unroll 1
        for(int si=0;si<2;si++){
            gemmTB(Xs, S_w2[3+si][b], Bt, acc);
            const float* wsk = S_wsk[si][b];
            const float* w1v = S_w1v[si][b];
            #pragma unroll
            for(int r=0;r<4;r++){
                const int r2 = rw*4+r;
                float p = 0.f;
                #pragma unroll
                for(int jj=0;jj<4;jj++){
                    const int col = jh*128 + tx + 32*jj;
                    float h = geluf(red2(acc[r][jj]));
                    p += Xs[r2*SA + col]*wsk[col] + h*w1v[col];
                }
                p = warp_sum(p);
                if(tx==0) Red[r2*2 + jh] = p;
            }
            __syncthreads();
            if(jh==0 && tx==0){
                #pragma unroll
                for(int r=0;r<4;r++){
                    const int r2 = rw*4+r, row = th*16 + r2;
                    float pt = Red[r2*2] + Red[r2*2+1];
                    if(si==0){ float sp = (pt>20.f)? pt : log1pf(expf(pt)); SC_eta[b][row] = sp*0.001f; }
                    else       SC_alpha[b][row] = 1.f/(1.f+expf(-pt));
                }
            }
            __syncthreads();
        }
    }
}

// ---------------- K2: mma heavy (128) + SIMT small (64) + mma o (32) ----------------
__global__ void __launch_bounds__(256) k2_token(float* __restrict__ dout, int chunk){
    extern __shared__ float sm[];
    const int tid = threadIdx.x, tx = tid&31;
    const int bx = blockIdx.x;

    if(bx < 128){
        float* Ah = sm;
        float* Al = sm + OF_AL;
        float* Wh = sm + OF_WH;
        float* Wl = sm + OF_WL;
        const int th = bx&3, f = (bx>>2)&3, b = bx>>4;
        const int s = (f==3)? 5 : f;
        const int w = tid>>5, g = tx>>2, tig = tx&3;
        const float* Kg = SC_k[b] + th*16*DD;
        const float* Vg = SC_v[b] + th*16*DD;

        splitA(Ah, Al, Kg);

        float acc[4][4], dz[4][4];
        mgemm<1>(Ah, Al, S_w2[s][b], Wh, Wl, acc);
        #pragma unroll
        for(int t=0;t<4;t++)
            #pragma unroll
            for(int e=0;e<4;e++){
                const int r = g + ((e>>1)<<3);
                const int j = w*32 + t*8 + 2*tig + (e&1);
                float z = acc[t][e];
                float h = geluf(z);
                dz[t][e] = dgeluf(z);
                SC_h2[s][b][(th*16 + r)*DD + j] = h;
                float hh = tf32hi(h);
                Ah[r*SA + j] = hh;
                Al[r*SA + j] = h - hh;
            }
        mgemm<1>(Ah, Al, S_w1f[f][b], Wh, Wl, acc);
        #pragma unroll
        for(int t=0;t<4;t++)
            #pragma unroll
            for(int e=0;e<4;e++){
                const int r = g + ((e>>1)<<3);
                const int j = w*32 + t*8 + 2*tig + (e&1);
                float gg = 2.f*(Kg[(size_t)r*DD + j] + acc[t][e] - Vg[(size_t)r*DD + j]);
                SC_g[f][b][(th*16 + r)*DD + j] = gg;
                float gh = tf32hi(gg);
                Ah[r*SA + j] = gh;
                Al[r*SA + j] = gg - gh;
            }
        mgemm<0>(Ah, Al, S_w1f[f][b], Wh, Wl, acc);
        #pragma unroll
        for(int t=0;t<4;t++)
            #pragma unroll
            for(int e=0;e<4;e++){
                const int r = g + ((e>>1)<<3);
                const int j = w*32 + t*8 + 2*tig + (e&1);
                SC_pre[s][b][(th*16 + r)*DD + j] = acc[t][e]*dz[t][e];
            }
    } else if(bx < 192){
        const int rw = (tid>>5)&3, jh = tid>>7;
        float* Ks  = sm;
        float* Bt  = sm + XTILE;
        float* Red = sm + XTILE + BT2;
        const int i = bx-128, th = i&3, si = (i>>2)&1, b = i>>3;
        const int s = 3+si;

        load_tile16(Ks, SC_k[b] + th*16*DD);
        u64 acc[4][4];
        gemmTB(Ks, S_w2[s][b], Bt, acc);
        const float* wsk = S_wsk[si][b];
        const float* w1v = S_w1v[si][b];
        float zr[4][4];
        #pragma unroll
        for(int r=0;r<4;r++){
            const int r2 = rw*4+r;
            float p = 0.f;
            #pragma unroll
            for(int jj=0;jj<4;jj++){
                const int col = jh*128 + tx + 32*jj;
                float z = red2(acc[r][jj]); zr[r][jj] = z;
                float h = geluf(z);
                SC_h2[s][b][(th*16 + r2)*DD + col] = h;
                p += Ks[r2*SA + col]*wsk[col] + h*w1v[col];
            }
            p = warp_sum(p);
            if(tx==0) Red[r2*2 + jh] = p;
        }
        __syncthreads();
        #pragma unroll
        for(int r=0;r<4;r++){
            const int r2 = rw*4+r, row = th*16 + r2;
            float pt = Red[r2*2] + Red[r2*2+1];
            float g = 2.f*(256.f*pt - SC_vsum[b][row]);
            if(jh==0 && tx==0) SC_gs[si][b][row] = g;
            #pragma unroll
            for(int jj=0;jj<4;jj++){
                const int col = jh*128 + tx + 32*jj;
                SC_pre[s][b][row*DD + col] = g * w1v[col] * dgeluf(zr[r][jj]);
            }
        }
    } else {
        float* Ah = sm;
        float* Al = sm + OF_AL;
        float* Wh = sm + OF_WH;
        float* Wl = sm + OF_WL;
        const int i = bx-192, th = i&3, b = i>>2;
        const int w = tid>>5, g = tx>>2, tig = tx&3;
        const float* Qg = SC_q[b] + th*16*DD;

        splitA(Ah, Al, Qg);

        float acc[4][4];
        mgemm<1>(Ah, Al, S_w2[5][b], Wh, Wl, acc);
        #pragma unroll
        for(int t=0;t<4;t++)
            #pragma unroll
            for(int e=0;e<4;e++){
                const int r = g + ((e>>1)<<3);
                const int j = w*32 + t*8 + 2*tig + (e&1);
                float h = geluf(acc[t][e]);
                float hh = tf32hi(h);
                Ah[r*SA + j] = hh;
                Al[r*SA + j] = h - hh;
            }
        mgemm<1>(Ah, Al, S_w1f[3][b], Wh, Wl, acc);
        #pragma unroll
        for(int t=0;t<4;t++)
            #pragma unroll
            for(int e=0;e<4;e++){
                const int r = g + ((e>>1)<<3);
                const int j = w*32 + t*8 + 2*tig + (e&1);
                size_t off = ((size_t)b*TLEN + (size_t)chunk*CHK + th*16 + r)*DD + j;
                dout[off] = Qg[(size_t)r*DD + j] + acc[t][e];
            }
        if(th==0 && tid==0){
            float p = 1.f;
            #pragma unroll
            for(int t=0;t<CHK;t++) p *= SC_alpha[b][t];
            SC_abar[b] = p;
        }
    }
}

// ---------------- K3: IN-PLACE weight updates (grid 656 x 256thr) [R7 exact] --------
__global__ void __launch_bounds__(256) k3_weights(){
    extern __shared__ float sm[];
    float* Ges = sm;
    float* Bs  = sm + 64*66;
    const int tid = threadIdx.x, wid = tid>>5, tx = tid&31;
    const int bx = blockIdx.x;

    if(bx < 640){
        int b, ot, ch;
        const float *A, *Bsrc; float* W;
        if(bx < 512){
            b = bx>>6; int r = bx&63;
            int f = r>>4, m = (r>>3)&1; ot = (r>>1)&3; ch = r&1;
            int s = (f==3)? 5 : f;
            if(m==0){ A = SC_g[f][b];   Bsrc = SC_h2[s][b]; W = S_w1f[f][b]; }
            else    { A = SC_pre[s][b]; Bsrc = SC_k[b];     W = S_w2[s][b];  }
        } else {
            int i = bx-512; b = i>>4; int r = i&15;
            int si = r>>3; ot = (r>>1)&3; ch = r&1;
            A = SC_pre[3+si][b]; Bsrc = SC_k[b]; W = S_w2[3+si][b];
        }
        const float abar = SC_abar[b];
        const float* eta = SC_eta[b];

        #pragma unroll
        for(int l=0;l<8;l++){
            int idx = tid + l*256;
            int t = idx>>5, qc = (idx&31)<<2;
            *reinterpret_cast<float4*>(Bs + t*132 + qc) =
                *reinterpret_cast<const float4*>(Bsrc + t*DD + ch*128 + qc);
        }
        #pragma unroll
        for(int l=0;l<4;l++){
            int idx = tid + l*256;
            int t = idx>>4, oq = (idx&15)<<2;
            float e = eta[t];
            float4 v = *reinterpret_cast<const float4*>(A + t*DD + ot*64 + oq);
            float2* p = reinterpret_cast<float2*>(Ges + t*66 + oq);
            p[0] = make_float2(v.x*e, v.y*e);
            p[1] = make_float2(v.z*e, v.w*e);
        }
        __syncthreads();

        u64 acc[4][4];
        #pragma unroll
        for(int rp=0;rp<4;rp++)
            #pragma unroll
            for(int j=0;j<4;j++) acc[rp][j] = 0ull;

        #pragma unroll 4
        for(int t=0;t<64;t++){
            u64 a[4];
            #pragma unroll
            for(int rp=0;rp<4;rp++)
                a[rp] = *reinterpret_cast<const u64*>(Ges + t*66 + wid*8 + 2*rp);
            float4 bv = *reinterpret_cast<const float4*>(Bs + t*132 + tx*4);
            u64 b0 = pk2(bv.x,bv.x), b1 = pk2(bv.y,bv.y), b2 = pk2(bv.z,bv.z), b3 = pk2(bv.w,bv.w);
            #pragma unroll
            for(int rp=0;rp<4;rp++){
                fmaX2(acc[rp][0], a[rp], b0);
                fmaX2(acc[rp][1], a[rp], b1);
                fmaX2(acc[rp][2], a[rp], b2);
                fmaX2(acc[rp][3], a[rp], b3);
            }
        }
        #pragma unroll
        for(int rp=0;rp<4;rp++){
            const int row0 = ot*64 + wid*8 + 2*rp;
            size_t off0 = (size_t)row0*DD + ch*128 + tx*4;
            float4 w0 = *reinterpret_cast<const float4*>(W + off0);
            float4 w1 = *reinterpret_cast<const float4*>(W + off0 + DD);
            float2 c0 = up2(acc[rp][0]), c1 = up2(acc[rp][1]);
            float2 c2 = up2(acc[rp][2]), c3 = up2(acc[rp][3]);
            *reinterpret_cast<float4*>(W + off0) =
                make_float4(abar*w0.x - c0.x, abar*w0.y - c1.x,
                            abar*w0.z - c2.x, abar*w0.w - c3.x);
            *reinterpret_cast<float4*>(W + off0 + DD) =
                make_float4(abar*w1.x - c0.y, abar*w1.y - c1.y,
                            abar*w1.z - c2.y, abar*w1.w - c3.y);
        }
    } else {
        const int i = bx-640, b = i>>1, si = i&1, s = 3+si;
        const float abar = SC_abar[b];
        const int j = tid;
        float aA = 0.f, aB = 0.f;
        #pragma unroll 4
        for(int t=0;t<CHK;t++){
            float ge = SC_gs[si][b][t]*SC_eta[b][t];
            aA += ge * SC_h2[s][b][t*DD + j];
            aB += ge * SC_k[b][t*DD + j];
        }
        S_w1v[si][b][j] = abar*S_w1v[si][b][j] - aA;
        S_wsk[si][b][j] = abar*S_wsk[si][b][j] - aB;
    }
}

// ---------------- launch ----------------
#define SMEM3 ((64*66 + 64*132)*4)           //  50688 B

extern "C" void kernel_launch(void* const* d_in, const int* in_sizes, int n_in,
                              void* d_out, int out_size){
    (void)in_sizes; (void)n_in; (void)out_size;
    const float* x   = (const float*)d_in[0];
    const float* k1w = (const float*)d_in[1];
    const float* k2w = (const float*)d_in[2];
    const float* v1w = (const float*)d_in[3];
    const float* v2w = (const float*)d_in[4];
    const float* q1w = (const float*)d_in[5];
    const float* q2w = (const float*)d_in[6];
    const float* e1w = (const float*)d_in[7];
    const float* e2w = (const float*)d_in[8];
    const float* esw = (const float*)d_in[9];
    const float* a1w = (const float*)d_in[10];
    const float* a2w = (const float*)d_in[11];
    const float* asw = (const float*)d_in[12];
    const float* m1w = (const float*)d_in[13];
    const float* m2w = (const float*)d_in[14];
    float* out = (float*)d_out;

    cudaFuncSetAttribute(k1_forward, cudaFuncAttributeMaxDynamicSharedMemorySize, SMEMK);
    cudaFuncSetAttribute(k2_token,   cudaFuncAttributeMaxDynamicSharedMemorySize, SMEMK);
    cudaFuncSetAttribute(k3_weights, cudaFuncAttributeMaxDynamicSharedMemorySize, SMEM3);

    k0_init<<<dim3(DD*DD/256, 11), 256>>>(k1w,k2w,v1w,v2w,q1w,q2w,e1w,e2w,esw,a1w,a2w,asw,m1w,m2w);

    for(int c=0;c<NC;c++){
        k1_forward<<<128, 256, SMEMK>>>(x, c);
        k2_token  <<<224, 256, SMEMK>>>(out, c);
        k3_weights<<<656, 256, SMEM3>>>();
    }
}

// round 16
// speedup vs baseline: 1.0487x; 1.0487x over previous
#include <cuda_runtime.h>
#include <math.h>
#include <stdint.h>

typedef unsigned long long u64;

#define DD   256
#define BB   8
#define CHK  64
#define NC   64
#define TLEN 4096

#define SA    260
#define STB   34
#define SNB   260
#define XTILE (16*SA)
#define BT2   17408

// k2-heavy mma smem layout (floats): Ah, Al, Ws(raw W panel)
#define OF_AL 4160
#define OF_WS 8320
#define SM2F  26752                  // 107008 B (o-path needs 2*XTILE+BT2 = 102912 B)

// ---------------- persistent state (in-place) ----------------
static __device__ float S_w1f[4][BB][DD*DD];
static __device__ float S_w2 [6][BB][DD*DD];
static __device__ float S_w1v[2][BB][DD];
static __device__ float S_wsk[2][BB][DD];

// ---------------- per-chunk scratch ----------------
static __device__ float SC_k [BB][CHK*DD];
static __device__ float SC_v [BB][CHK*DD];
static __device__ float SC_q [BB][CHK*DD];
static __device__ float SC_h2[6][BB][CHK*DD];
static __device__ float SC_g [4][BB][CHK*DD];
static __device__ float SC_pre[6][BB][CHK*DD];
static __device__ float SC_eta[BB][CHK];
static __device__ float SC_alpha[BB][CHK];
static __device__ float SC_vsum[BB][CHK];
static __device__ float SC_gs[2][BB][CHK];
static __device__ float SC_abar[BB];

// ---------------- helpers ----------------
__device__ __forceinline__ void fmaX2(u64 &d, u64 a, u64 b){
    asm("fma.rn.f32x2 %0, %1, %2, %0;" : "+l"(d) : "l"(a), "l"(b));
}
__device__ __forceinline__ u64 pk2(float lo, float hi){
    u64 r; asm("mov.b64 %0, {%1, %2};" : "=l"(r) : "f"(lo), "f"(hi)); return r;
}
__device__ __forceinline__ float2 up2(u64 v){
    float lo, hi; asm("mov.b64 {%0, %1}, %2;" : "=f"(lo), "=f"(hi) : "l"(v));
    return make_float2(lo, hi);
}
__device__ __forceinline__ float red2(u64 v){ float2 t = up2(v); return t.x + t.y; }
__device__ __forceinline__ float geluf(float z){
    return 0.5f*z*(1.0f + erff(z*0.70710678118654752f));
}
__device__ __forceinline__ float dgeluf(float z){
    float cdf = 0.5f*(1.0f + erff(z*0.70710678118654752f));
    float pdf = expf(-0.5f*z*z)*0.39894228040143267f;
    return cdf + z*pdf;
}
__device__ __forceinline__ float warp_sum(float v){
    #pragma unroll
    for(int o=16;o>0;o>>=1) v += __shfl_xor_sync(0xffffffffu, v, o);
    return v;
}
__device__ __forceinline__ float tf32hi(float f){
    uint32_t h; asm("cvt.rna.tf32.f32 %0, %1;" : "=r"(h) : "f"(f));
    return __uint_as_float(h);
}
__device__ __forceinline__ void mma8(float (&c)[4], const uint32_t (&a)[4],
                                     uint32_t b0, uint32_t b1){
    asm volatile("mma.sync.aligned.m16n8k8.row.col.f32.tf32.tf32.f32 "
        "{%0,%1,%2,%3}, {%4,%5,%6,%7}, {%8,%9}, {%0,%1,%2,%3};"
        : "+f"(c[0]),"+f"(c[1]),"+f"(c[2]),"+f"(c[3])
        : "r"(a[0]),"r"(a[1]),"r"(a[2]),"r"(a[3]), "r"(b0),"r"(b1));
}

__device__ __forceinline__ void load_tile16(float* dst, const float* __restrict__ src){
    const int tid = threadIdx.x;
    #pragma unroll
    for(int l=0;l<4;l++){
        int idx = tid + l*256;
        int r = idx>>6, qc = (idx&63)<<2;
        *reinterpret_cast<float4*>(dst + r*SA + qc) =
            *reinterpret_cast<const float4*>(src + r*DD + qc);
    }
}

// ---------------- SIMT TB GEMM (R7-proven) ----------------
__device__ __forceinline__ void gemmTB(const float* As, const float* __restrict__ Bg,
                                       float* Bt, u64 (&acc)[4][4]){
    const int tid = threadIdx.x, tx = tid&31;
    const int rw = (tid>>5)&3, jh = tid>>7;
    const int j0 = tid>>3, qc = (tid&7)<<2;
    #pragma unroll
    for(int r=0;r<4;r++)
        #pragma unroll
        for(int j=0;j<4;j++) acc[r][j] = 0ull;

    float4 rb[8];
    #pragma unroll
    for(int l=0;l<8;l++)
        rb[l] = *reinterpret_cast<const float4*>(Bg + (size_t)(j0+32*l)*DD + qc);
    #pragma unroll
    for(int l=0;l<8;l++){
        float2* p = reinterpret_cast<float2*>(Bt + (j0+32*l)*STB + qc);
        p[0] = make_float2(rb[l].x, rb[l].y);
        p[1] = make_float2(rb[l].z, rb[l].w);
    }
    __syncthreads();

    #pragma unroll 2
    for(int p=0;p<8;p++){
        if(p<7){
            const float* src = Bg + (p+1)*32 + qc;
            #pragma unroll
            for(int l=0;l<8;l++)
                rb[l] = *reinterpret_cast<const float4*>(src + (size_t)(j0+32*l)*DD);
        }
        const float* Ar = As + rw*4*SA + p*32;
        const float* Bl = Bt + (p&1)*256*STB + (jh*128 + tx)*STB;
        #pragma unroll
        for(int c2=0;c2<16;c2++){
            u64 a0 = *reinterpret_cast<const u64*>(Ar + 0*SA + 2*c2);
            u64 a1 = *reinterpret_cast<const u64*>(Ar + 1*SA + 2*c2);
            u64 a2 = *reinterpret_cast<const u64*>(Ar + 2*SA + 2*c2);
            u64 a3 = *reinterpret_cast<const u64*>(Ar + 3*SA + 2*c2);
            #pragma unroll
            for(int jj=0;jj<4;jj++){
                u64 b = *reinterpret_cast<const u64*>(Bl + jj*32*STB + 2*c2);
                fmaX2(acc[0][jj], a0, b);
                fmaX2(acc[1][jj], a1, b);
                fmaX2(acc[2][jj], a2, b);
                fmaX2(acc[3][jj], a3, b);
            }
        }
        if(p<7){
            float* dstb = Bt + ((p+1)&1)*256*STB;
            #pragma unroll
            for(int l=0;l<8;l++){
                float2* q = reinterpret_cast<float2*>(dstb + (j0+32*l)*STB + qc);
                q[0] = make_float2(rb[l].x, rb[l].y);
                q[1] = make_float2(rb[l].z, rb[l].w);
            }
            __syncthreads();
        }
    }
}

// ---------------- tf32 mma GEMM, raw-W staging (k2-heavy only) ----------------
// OUT[t,j] = sum_c A[t,c]*W[j,c] (TB=1) or sum_c A[t,c]*W[c,j] (TB=0).
// 256 thr: warp w -> cols w*32..+31 (4 n8-tiles); m16 = 16 tokens.
// W staged RAW (one plane); hi/lo tf32 split computed at fragment-load time.
template<int TB>
__device__ __forceinline__ void mgemm(const float* Ah, const float* Al,
                                      const float* __restrict__ Wg,
                                      float* Ws, float (&acc)[4][4]){
    const int tid = threadIdx.x, tx = tid&31;
    const int w = tid>>5, g = tx>>2, tig = tx&3;
    #pragma unroll
    for(int t=0;t<4;t++)
        #pragma unroll
        for(int e=0;e<4;e++) acc[t][e] = 0.f;

    for(int p=0;p<8;p++){
        __syncthreads();
        #pragma unroll
        for(int l=0;l<8;l++){
            int idx = tid + l*256;
            float4 v;
            uint32_t o;
            if(TB){
                int j = idx>>3, qc = (idx&7)<<2;
                v = *reinterpret_cast<const float4*>(Wg + (size_t)j*DD + p*32 + qc);
                o = (uint32_t)(j*36 + qc);
            } else {
                int cc = idx>>6, qn = (idx&63)<<2;
                v = *reinterpret_cast<const float4*>(Wg + (size_t)(p*32+cc)*DD + qn);
                o = (uint32_t)(cc*264 + qn);
            }
            *reinterpret_cast<float4*>(Ws + o) = v;
        }
        __syncthreads();
        #pragma unroll
        for(int ks=0;ks<4;ks++){
            const int kk = p*32 + ks*8;
            uint32_t ah[4], al[4];
            const float* A0 = Ah + g*SA + kk + tig;
            const float* A1 = Al + g*SA + kk + tig;
            ah[0] = __float_as_uint(A0[0]);
            ah[1] = __float_as_uint(A0[8*SA]);
            ah[2] = __float_as_uint(A0[4]);
            ah[3] = __float_as_uint(A0[8*SA+4]);
            al[0] = __float_as_uint(A1[0]);
            al[1] = __float_as_uint(A1[8*SA]);
            al[2] = __float_as_uint(A1[4]);
            al[3] = __float_as_uint(A1[8*SA+4]);
            #pragma unroll
            for(int t=0;t<4;t++){
                const int jn = w*32 + t*8 + g;
                float w0, w1;
                if(TB){
                    const float* P = Ws + jn*36 + ks*8 + tig;
                    w0 = P[0]; w1 = P[4];
                } else {
                    const float* P = Ws + (ks*8+tig)*264 + jn;
                    w0 = P[0]; w1 = P[4*264];
                }
                float h0 = tf32hi(w0), h1 = tf32hi(w1);
                uint32_t bh0 = __float_as_uint(h0), bh1 = __float_as_uint(h1);
                uint32_t bl0 = __float_as_uint(w0 - h0), bl1 = __float_as_uint(w1 - h1);
                mma8(acc[t], ah, bh0, bh1);
                mma8(acc[t], al, bh0, bh1);
                mma8(acc[t], ah, bl0, bl1);
            }
        }
    }
    __syncthreads();
}

// ---------------- K0 ----------------
__global__ void k0_init(const float* __restrict__ k1w, const float* __restrict__ k2w,
                        const float* __restrict__ v1w, const float* __restrict__ v2w,
                        const float* __restrict__ q1w, const float* __restrict__ q2w,
                        const float* __restrict__ e1w, const float* __restrict__ e2w,
                        const float* __restrict__ esw, const float* __restrict__ a1w,
                        const float* __restrict__ a2w, const float* __restrict__ asw,
                        const float* __restrict__ m1w, const float* __restrict__ m2w){
    const int gid = blockIdx.x*blockDim.x + threadIdx.x;
    const int m = blockIdx.y;
    if(m<4){
        const float* src = (m==0)?k1w:(m==1)?v1w:(m==2)?q1w:m1w;
        float v = src[gid];
        #pragma unroll
        for(int b=0;b<BB;b++) S_w1f[m][b][gid] = v;
    } else if(m<10){
        const int s = m-4;
        const float* src = (s==0)?k2w:(s==1)?v2w:(s==2)?q2w:(s==3)?e2w:(s==4)?a2w:m2w;
        float v = src[gid];
        #pragma unroll
        for(int b=0;b<BB;b++) S_w2[s][b][gid] = v;
    } else {
        if(gid < DD){
            #pragma unroll
            for(int b=0;b<BB;b++){
                S_w1v[0][b][gid] = e1w[gid];
                S_w1v[1][b][gid] = a1w[gid];
                S_wsk[0][b][gid] = esw[gid];
                S_wsk[1][b][gid] = asw[gid];
            }
        }
    }
}

// ---------------- K1 (R7 SIMT, grid 128 x 256thr) ----------------
__global__ void __launch_bounds__(256) k1_forward(const float* __restrict__ x, int chunk){
    extern __shared__ float sm[];
    float* Xs  = sm;
    float* Hs  = sm + XTILE;
    float* Bt  = sm + 2*XTILE;
    float* Red = sm + 2*XTILE + BT2;
    const int tid = threadIdx.x, tx = tid&31;
    const int rw = (tid>>5)&3, jh = tid>>7;
    const int bx = blockIdx.x;
    const int th = bx&3, gg = (bx>>2)&3, b = bx>>4;
    const int tok0 = chunk*CHK + th*16;

    load_tile16(Xs, x + ((size_t)b*TLEN + tok0)*DD);

    u64 acc[4][4];
    if(gg < 3){
        gemmTB(Xs, S_w2[gg][b], Bt, acc);
        __syncthreads();
        #pragma unroll
        for(int r=0;r<4;r++)
            #pragma unroll
            for(int jj=0;jj<4;jj++)
                Hs[(rw*4+r)*SA + jh*128 + tx + 32*jj] = geluf(red2(acc[r][jj]));
        gemmTB(Hs, S_w1f[gg][b], Bt, acc);

        float out[4][4];
        #pragma unroll
        for(int r=0;r<4;r++){
            const int r2 = rw*4+r;
            float s = 0.f;
            #pragma unroll
            for(int jj=0;jj<4;jj++){
                const int col = jh*128 + tx + 32*jj;
                float o = Xs[r2*SA + col] + red2(acc[r][jj]);
                out[r][jj] = o;
                s += (gg==1)? o : o*o;
            }
            s = warp_sum(s);
            if(tx==0) Red[r2*2 + jh] = s;
        }
        __syncthreads();
        if(gg==1){
            #pragma unroll
            for(int r=0;r<4;r++){
                const int r2 = rw*4+r, row = th*16 + r2;
                #pragma unroll
                for(int jj=0;jj<4;jj++)
                    SC_v[b][row*DD + jh*128 + tx + 32*jj] = out[r][jj];
                if(jh==0 && tx==0) SC_vsum[b][row] = Red[r2*2] + Red[r2*2+1];
            }
        } else {
            float* dst = (gg==0)? SC_k[b] : SC_q[b];
            #pragma unroll
            for(int r=0;r<4;r++){
                const int r2 = rw*4+r, row = th*16 + r2;
                float inv = 1.f / fmaxf(sqrtf(Red[r2*2] + Red[r2*2+1]), 1e-6f);
                #pragma unroll
                for(int jj=0;jj<4;jj++)
                    dst[row*DD + jh*128 + tx + 32*jj] = out[r][jj]*inv;
            }
        }
    } else {
        #pragma unroll 1
        for(int si=0;si<2;si++){
            gemmTB(Xs, S_w2[3+si][b], Bt, acc);
            const float* wsk = S_wsk[si][b];
            const float* w1v = S_w1v[si][b];
            #pragma unroll
            for(int r=0;r<4;r++){
                const int r2 = rw*4+r;
                float p = 0.f;
                #pragma unroll
                for(int jj=0;jj<4;jj++){
                    const int col = jh*128 + tx + 32*jj;
                    float h = geluf(red2(acc[r][jj]));
                    p += Xs[r2*SA + col]*wsk[col] + h*w1v[col];
                }
                p = warp_sum(p);
                if(tx==0) Red[r2*2 + jh] = p;
            }
            __syncthreads();
            if(jh==0 && tx==0){
                #pragma unroll
                for(int r=0;r<4;r++){
                    const int r2 = rw*4+r, row = th*16 + r2;
                    float pt = Red[r2*2] + Red[r2*2+1];
                    if(si==0){ float sp = (pt>20.f)? pt : log1pf(expf(pt)); SC_eta[b][row] = sp*0.001f; }
                    else       SC_alpha[b][row] = 1.f/(1.f+expf(-pt));
                }
            }
            __syncthreads();
        }
    }
}

// ---------------- K2: mma heavy (128) + SIMT small (64) + SIMT o (32) ----------------
__global__ void __launch_bounds__(256) k2_token(float* __restrict__ dout, int chunk){
    extern __shared__ float sm[];
    const int tid = threadIdx.x, tx = tid&31;
    const int bx = blockIdx.x;

    if(bx < 128){
        float* Ah = sm;
        float* Al = sm + OF_AL;
        float* Ws = sm + OF_WS;
        const int th = bx&3, f = (bx>>2)&3, b = bx>>4;
        const int s = (f==3)? 5 : f;
        const int w = tid>>5, g = tx>>2, tig = tx&3;
        const float* Kg = SC_k[b] + th*16*DD;
        const float* Vg = SC_v[b] + th*16*DD;

        // load + split K tile into hi/lo activation planes
        #pragma unroll
        for(int l=0;l<4;l++){
            int idx = tid + l*256;
            int r = idx>>6, qc = (idx&63)<<2;
            float4 v = *reinterpret_cast<const float4*>(Kg + (size_t)r*DD + qc);
            float4 h, lo;
            h.x = tf32hi(v.x); lo.x = v.x - h.x;
            h.y = tf32hi(v.y); lo.y = v.y - h.y;
            h.z = tf32hi(v.z); lo.z = v.z - h.z;
            h.w = tf32hi(v.w); lo.w = v.w - h.w;
            *reinterpret_cast<float4*>(Ah + r*SA + qc) = h;
            *reinterpret_cast<float4*>(Al + r*SA + qc) = lo;
        }

        float acc[4][4], dz[4][4];
        // gemm1: z = K @ W2^T
        mgemm<1>(Ah, Al, S_w2[s][b], Ws, acc);
        #pragma unroll
        for(int t=0;t<4;t++)
            #pragma unroll
            for(int e=0;e<4;e++){
                const int r = g + ((e>>1)<<3);
                const int j = w*32 + t*8 + 2*tig + (e&1);
                float z = acc[t][e];
                float h = geluf(z);
                dz[t][e] = dgeluf(z);
                SC_h2[s][b][(th*16 + r)*DD + j] = h;
                float hh = tf32hi(h);
                Ah[r*SA + j] = hh;
                Al[r*SA + j] = h - hh;
            }
        // gemm2: fval = H @ W1^T ; g = 2(k + f - v)
        mgemm<1>(Ah, Al, S_w1f[f][b], Ws, acc);
        #pragma unroll
        for(int t=0;t<4;t++)
            #pragma unroll
            for(int e=0;e<4;e++){
                const int r = g + ((e>>1)<<3);
                const int j = w*32 + t*8 + 2*tig + (e&1);
                float gg = 2.f*(Kg[(size_t)r*DD + j] + acc[t][e] - Vg[(size_t)r*DD + j]);
                SC_g[f][b][(th*16 + r)*DD + j] = gg;
                float gh = tf32hi(gg);
                Ah[r*SA + j] = gh;
                Al[r*SA + j] = gg - gh;
            }
        // gemm3: pre = (G @ W1) * dgelu(z)
        mgemm<0>(Ah, Al, S_w1f[f][b], Ws, acc);
        #pragma unroll
        for(int t=0;t<4;t++)
            #pragma unroll
            for(int e=0;e<4;e++){
                const int r = g + ((e>>1)<<3);
                const int j = w*32 + t*8 + 2*tig + (e&1);
                SC_pre[s][b][(th*16 + r)*DD + j] = acc[t][e]*dz[t][e];
            }
    } else if(bx < 192){
        const int rw = (tid>>5)&3, jh = tid>>7;
        float* Ks  = sm;
        float* Bt  = sm + XTILE;
        float* Red = sm + XTILE + BT2;
        const int i = bx-128, th = i&3, si = (i>>2)&1, b = i>>3;
        const int s = 3+si;

        load_tile16(Ks, SC_k[b] + th*16*DD);
        u64 acc[4][4];
        gemmTB(Ks, S_w2[s][b], Bt, acc);
        const float* wsk = S_wsk[si][b];
        const float* w1v = S_w1v[si][b];
        float zr[4][4];
        #pragma unroll
        for(int r=0;r<4;r++){
            const int r2 = rw*4+r;
            float p = 0.f;
            #pragma unroll
            for(int jj=0;jj<4;jj++){
                const int col = jh*128 + tx + 32*jj;
                float z = red2(acc[r][jj]); zr[r][jj] = z;
                float h = geluf(z);
                SC_h2[s][b][(th*16 + r2)*DD + col] = h;
                p += Ks[r2*SA + col]*wsk[col] + h*w1v[col];
            }
            p = warp_sum(p);
            if(tx==0) Red[r2*2 + jh] = p;
        }
        __syncthreads();
        #pragma unroll
        for(int r=0;r<4;r++){
            const int r2 = rw*4+r, row = th*16 + r2;
            float pt = Red[r2*2] + Red[r2*2+1];
            float g = 2.f*(256.f*pt - SC_vsum[b][row]);
            if(jh==0 && tx==0) SC_gs[si][b][row] = g;
            #pragma unroll
            for(int jj=0;jj<4;jj++){
                const int col = jh*128 + tx + 32*jj;
                SC_pre[s][b][row*DD + col] = g * w1v[col] * dgeluf(zr[r][jj]);
            }
        }
    } else {
        const int rw = (tid>>5)&3, jh = tid>>7;
        float* Qs = sm;
        float* Hs = sm + XTILE;
        float* Bt = sm + 2*XTILE;
        const int i = bx-192, th = i&3, b = i>>2;

        load_tile16(Qs, SC_q[b] + th*16*DD);
        u64 acc[4][4];
        gemmTB(Qs, S_w2[5][b], Bt, acc);
        __syncthreads();
        #pragma unroll
        for(int r=0;r<4;r++)
            #pragma unroll
            for(int jj=0;jj<4;jj++)
                Hs[(rw*4+r)*SA + jh*128 + tx + 32*jj] = geluf(red2(acc[r][jj]));
        gemmTB(Hs, S_w1f[3][b], Bt, acc);
        #pragma unroll
        for(int r=0;r<4;r++)
            #pragma unroll
            for(int jj=0;jj<4;jj++){
                const int r2 = rw*4+r, col = jh*128 + tx + 32*jj;
                size_t off = ((size_t)b*TLEN + (size_t)chunk*CHK + th*16 + r2)*DD + col;
                dout[off] = Qs[r2*SA + col] + red2(acc[r][jj]);
            }
        if(th==0 && tid==0){
            float p = 1.f;
            #pragma unroll
            for(int t=0;t<CHK;t++) p *= SC_alpha[b][t];
            SC_abar[b] = p;
        }
    }
}

// ---------------- K3: IN-PLACE weight updates (grid 656 x 256thr) [R7 exact] --------
__global__ void __launch_bounds__(256) k3_weights(){
    extern __shared__ float sm[];
    float* Ges = sm;
    float* Bs  = sm + 64*66;
    const int tid = threadIdx.x, wid = tid>>5, tx = tid&31;
    const int bx = blockIdx.x;

    if(bx < 640){
        int b, ot, ch;
        const float *A, *Bsrc; float* W;
        if(bx < 512){
            b = bx>>6; int r = bx&63;
            int f = r>>4, m = (r>>3)&1; ot = (r>>1)&3; ch = r&1;
            int s = (f==3)? 5 : f;
            if(m==0){ A = SC_g[f][b];   Bsrc = SC_h2[s][b]; W = S_w1f[f][b]; }
            else    { A = SC_pre[s][b]; Bsrc = SC_k[b];     W = S_w2[s][b];  }
        } else {
            int i = bx-512; b = i>>4; int r = i&15;
            int si = r>>3; ot = (r>>1)&3; ch = r&1;
            A = SC_pre[3+si][b]; Bsrc = SC_k[b]; W = S_w2[3+si][b];
        }
        const float abar = SC_abar[b];
        const float* eta = SC_eta[b];

        #pragma unroll
        for(int l=0;l<8;l++){
            int idx = tid + l*256;
            int t = idx>>5, qc = (idx&31)<<2;
            *reinterpret_cast<float4*>(Bs + t*132 + qc) =
                *reinterpret_cast<const float4*>(Bsrc + t*DD + ch*128 + qc);
        }
        #pragma unroll
        for(int l=0;l<4;l++){
            int idx = tid + l*256;
            int t = idx>>4, oq = (idx&15)<<2;
            float e = eta[t];
            float4 v = *reinterpret_cast<const float4*>(A + t*DD + ot*64 + oq);
            float2* p = reinterpret_cast<float2*>(Ges + t*66 + oq);
            p[0] = make_float2(v.x*e, v.y*e);
            p[1] = make_float2(v.z*e, v.w*e);
        }
        __syncthreads();

        u64 acc[4][4];
        #pragma unroll
        for(int rp=0;rp<4;rp++)
            #pragma unroll
            for(int j=0;j<4;j++) acc[rp][j] = 0ull;

        #pragma unroll 4
        for(int t=0;t<64;t++){
            u64 a[4];
            #pragma unroll
            for(int rp=0;rp<4;rp++)
                a[rp] = *reinterpret_cast<const u64*>(Ges + t*66 + wid*8 + 2*rp);
            float4 bv = *reinterpret_cast<const float4*>(Bs + t*132 + tx*4);
            u64 b0 = pk2(bv.x,bv.x), b1 = pk2(bv.y,bv.y), b2 = pk2(bv.z,bv.z), b3 = pk2(bv.w,bv.w);
            #pragma unroll
            for(int rp=0;rp<4;rp++){
                fmaX2(acc[rp][0], a[rp], b0);
                fmaX2(acc[rp][1], a[rp], b1);
                fmaX2(acc[rp][2], a[rp], b2);
                fmaX2(acc[rp][3], a[rp], b3);
            }
        }
        #pragma unroll
        for(int rp=0;rp<4;rp++){
            const int row0 = ot*64 + wid*8 + 2*rp;
            size_t off0 = (size_t)row0*DD + ch*128 + tx*4;
            float4 w0 = *reinterpret_cast<const float4*>(W + off0);
            float4 w1 = *reinterpret_cast<const float4*>(W + off0 + DD);
            float2 c0 = up2(acc[rp][0]), c1 = up2(acc[rp][1]);
            float2 c2 = up2(acc[rp][2]), c3 = up2(acc[rp][3]);
            *reinterpret_cast<float4*>(W + off0) =
                make_float4(abar*w0.x - c0.x, abar*w0.y - c1.x,
                            abar*w0.z - c2.x, abar*w0.w - c3.x);
            *reinterpret_cast<float4*>(W + off0 + DD) =
                make_float4(abar*w1.x - c0.y, abar*w1.y - c1.y,
                            abar*w1.z - c2.y, abar*w1.w - c3.y);
        }
    } else {
        const int i = bx-640, b = i>>1, si = i&1, s = 3+si;
        const float abar = SC_abar[b];
        const int j = tid;
        float aA = 0.f, aB = 0.f;
        #pragma unroll 4
        for(int t=0;t<CHK;t++){
            float ge = SC_gs[si][b][t]*SC_eta[b][t];
            aA += ge * SC_h2[s][b][t*DD + j];
            aB += ge * SC_k[b][t*DD + j];
        }
        S_w1v[si][b][j] = abar*S_w1v[si][b][j] - aA;
        S_wsk[si][b][j] = abar*S_wsk[si][b][j] - aB;
    }
}

// ---------------- launch ----------------
#define SMEM1 ((2*XTILE + BT2 + 32)*4)       // 103168 B
#define SMEM2 (SM2F*4)                        // 107008 B
#define SMEM3 ((64*66 + 64*132)*4)           //  50688 B

extern "C" void kernel_launch(void* const* d_in, const int* in_sizes, int n_in,
                              void* d_out, int out_size){
    (void)in_sizes; (void)n_in; (void)out_size;
    const float* x   = (const float*)d_in[0];
    const float* k1w = (const float*)d_in[1];
    const float* k2w = (const float*)d_in[2];
    const float* v1w = (const float*)d_in[3];
    const float* v2w = (const float*)d_in[4];
    const float* q1w = (const float*)d_in[5];
    const float* q2w = (const float*)d_in[6];
    const float* e1w = (const float*)d_in[7];
    const float* e2w = (const float*)d_in[8];
    const float* esw = (const float*)d_in[9];
    const float* a1w = (const float*)d_in[10];
    const float* a2w = (const float*)d_in[11];
    const float* asw = (const float*)d_in[12];
    const float* m1w = (const float*)d_in[13];
    const float* m2w = (const float*)d_in[14];
    float* out = (float*)d_out;

    cudaFuncSetAttribute(k1_forward, cudaFuncAttributeMaxDynamicSharedMemorySize, SMEM1);
    cudaFuncSetAttribute(k2_token,   cudaFuncAttributeMaxDynamicSharedMemorySize, SMEM2);
    cudaFuncSetAttribute(k3_weights, cudaFuncAttributeMaxDynamicSharedMemorySize, SMEM3);

    k0_init<<<dim3(DD*DD/256, 11), 256>>>(k1w,k2w,v1w,v2w,q1w,q2w,e1w,e2w,esw,a1w,a2w,asw,m1w,m2w);

    for(int c=0;c<NC;c++){
        k1_forward<<<128, 256, SMEM1>>>(x, c);
        k2_token  <<<224, 256, SMEM2>>>(out, c);
        k3_weights<<<656, 256, SMEM3>>>();
    }
}

// round 17
// speedup vs baseline: 1.0612x; 1.0119x over previous
#include <cuda_runtime.h>
#include <math.h>
#include <stdint.h>

typedef unsigned long long u64;

#define DD   256
#define BB   8
#define CHK  64
#define NC   64
#define TLEN 4096

#define SA    260
#define STB   34
#define XTILE (16*SA)
#define BT2   17408

// k2-heavy mma smem layout (floats): Ah, Al, Ws (double-buffered raw W panel)
#define OF_AL 4160
#define OF_WS 8320
#define WPLANE 9216                  // TB: 256*36 ; N uses 32*264=8448 <= WPLANE
#define SM2F  26752                  // 107008 B

// ---------------- persistent state (in-place) ----------------
static __device__ float S_w1f[4][BB][DD*DD];
static __device__ float S_w2 [6][BB][DD*DD];
static __device__ float S_w1v[2][BB][DD];
static __device__ float S_wsk[2][BB][DD];

// ---------------- per-chunk scratch ----------------
static __device__ float SC_k [BB][CHK*DD];
static __device__ float SC_v [BB][CHK*DD];
static __device__ float SC_q [BB][CHK*DD];
static __device__ float SC_h2[6][BB][CHK*DD];
static __device__ float SC_g [4][BB][CHK*DD];
static __device__ float SC_pre[6][BB][CHK*DD];
static __device__ float SC_eta[BB][CHK];
static __device__ float SC_alpha[BB][CHK];
static __device__ float SC_vsum[BB][CHK];
static __device__ float SC_gs[2][BB][CHK];
static __device__ float SC_abar[BB];

// ---------------- helpers ----------------
__device__ __forceinline__ void fmaX2(u64 &d, u64 a, u64 b){
    asm("fma.rn.f32x2 %0, %1, %2, %0;" : "+l"(d) : "l"(a), "l"(b));
}
__device__ __forceinline__ u64 pk2(float lo, float hi){
    u64 r; asm("mov.b64 %0, {%1, %2};" : "=l"(r) : "f"(lo), "f"(hi)); return r;
}
__device__ __forceinline__ float2 up2(u64 v){
    float lo, hi; asm("mov.b64 {%0, %1}, %2;" : "=f"(lo), "=f"(hi) : "l"(v));
    return make_float2(lo, hi);
}
__device__ __forceinline__ float red2(u64 v){ float2 t = up2(v); return t.x + t.y; }
__device__ __forceinline__ float geluf(float z){
    return 0.5f*z*(1.0f + erff(z*0.70710678118654752f));
}
__device__ __forceinline__ float dgeluf(float z){
    float cdf = 0.5f*(1.0f + erff(z*0.70710678118654752f));
    float pdf = expf(-0.5f*z*z)*0.39894228040143267f;
    return cdf + z*pdf;
}
__device__ __forceinline__ float warp_sum(float v){
    #pragma unroll
    for(int o=16;o>0;o>>=1) v += __shfl_xor_sync(0xffffffffu, v, o);
    return v;
}
__device__ __forceinline__ float tf32hi(float f){
    uint32_t h; asm("cvt.rna.tf32.f32 %0, %1;" : "=r"(h) : "f"(f));
    return __uint_as_float(h);
}
__device__ __forceinline__ void mma8(float (&c)[4], const uint32_t (&a)[4],
                                     uint32_t b0, uint32_t b1){
    asm volatile("mma.sync.aligned.m16n8k8.row.col.f32.tf32.tf32.f32 "
        "{%0,%1,%2,%3}, {%4,%5,%6,%7}, {%8,%9}, {%0,%1,%2,%3};"
        : "+f"(c[0]),"+f"(c[1]),"+f"(c[2]),"+f"(c[3])
        : "r"(a[0]),"r"(a[1]),"r"(a[2]),"r"(a[3]), "r"(b0),"r"(b1));
}

__device__ __forceinline__ void load_tile16(float* dst, const float* __restrict__ src){
    const int tid = threadIdx.x;
    #pragma unroll
    for(int l=0;l<4;l++){
        int idx = tid + l*256;
        int r = idx>>6, qc = (idx&63)<<2;
        *reinterpret_cast<float4*>(dst + r*SA + qc) =
            *reinterpret_cast<const float4*>(src + r*DD + qc);
    }
}

// ---------------- SIMT TB GEMM (R7-proven) ----------------
__device__ __forceinline__ void gemmTB(const float* As, const float* __restrict__ Bg,
                                       float* Bt, u64 (&acc)[4][4]){
    const int tid = threadIdx.x, tx = tid&31;
    const int rw = (tid>>5)&3, jh = tid>>7;
    const int j0 = tid>>3, qc = (tid&7)<<2;
    #pragma unroll
    for(int r=0;r<4;r++)
        #pragma unroll
        for(int j=0;j<4;j++) acc[r][j] = 0ull;

    float4 rb[8];
    #pragma unroll
    for(int l=0;l<8;l++)
        rb[l] = *reinterpret_cast<const float4*>(Bg + (size_t)(j0+32*l)*DD + qc);
    #pragma unroll
    for(int l=0;l<8;l++){
        float2* p = reinterpret_cast<float2*>(Bt + (j0+32*l)*STB + qc);
        p[0] = make_float2(rb[l].x, rb[l].y);
        p[1] = make_float2(rb[l].z, rb[l].w);
    }
    __syncthreads();

    #pragma unroll 2
    for(int p=0;p<8;p++){
        if(p<7){
            const float* src = Bg + (p+1)*32 + qc;
            #pragma unroll
            for(int l=0;l<8;l++)
                rb[l] = *reinterpret_cast<const float4*>(src + (size_t)(j0+32*l)*DD);
        }
        const float* Ar = As + rw*4*SA + p*32;
        const float* Bl = Bt + (p&1)*256*STB + (jh*128 + tx)*STB;
        #pragma unroll
        for(int c2=0;c2<16;c2++){
            u64 a0 = *reinterpret_cast<const u64*>(Ar + 0*SA + 2*c2);
            u64 a1 = *reinterpret_cast<const u64*>(Ar + 1*SA + 2*c2);
            u64 a2 = *reinterpret_cast<const u64*>(Ar + 2*SA + 2*c2);
            u64 a3 = *reinterpret_cast<const u64*>(Ar + 3*SA + 2*c2);
            #pragma unroll
            for(int jj=0;jj<4;jj++){
                u64 b = *reinterpret_cast<const u64*>(Bl + jj*32*STB + 2*c2);
                fmaX2(acc[0][jj], a0, b);
                fmaX2(acc[1][jj], a1, b);
                fmaX2(acc[2][jj], a2, b);
                fmaX2(acc[3][jj], a3, b);
            }
        }
        if(p<7){
            float* dstb = Bt + ((p+1)&1)*256*STB;
            #pragma unroll
            for(int l=0;l<8;l++){
                float2* q = reinterpret_cast<float2*>(dstb + (j0+32*l)*STB + qc);
                q[0] = make_float2(rb[l].x, rb[l].y);
                q[1] = make_float2(rb[l].z, rb[l].w);
            }
            __syncthreads();
        }
    }
}

// ---------------- tf32 mma GEMM, raw-W + reg-staged double-buffered panels ----------
// OUT[t,j] = sum_c A[t,c]*W[j,c] (TB=1) or sum_c A[t,c]*W[c,j] (TB=0).
// 256 thr: warp w -> cols w*32..+31 (4 n8-tiles); m16 = 16 tokens.
template<int TB>
__device__ __forceinline__ void mgemm(const float* Ah, const float* Al,
                                      const float* __restrict__ Wg,
                                      float* Ws, float (&acc)[4][4]){
    const int tid = threadIdx.x, tx = tid&31;
    const int w = tid>>5, g = tx>>2, tig = tx&3;
    #pragma unroll
    for(int t=0;t<4;t++)
        #pragma unroll
        for(int e=0;e<4;e++) acc[t][e] = 0.f;

    // per-thread staging coords
    const int sj  = tid>>1,  sqc = (tid&1)<<2;     // TB: rows sj+128l? no: see below
    float4 rb[8];

    // preload panel 0
    #pragma unroll
    for(int l=0;l<8;l++){
        int idx = tid + l*256;
        if(TB){
            int j = idx>>3, qc = (idx&7)<<2;
            rb[l] = *reinterpret_cast<const float4*>(Wg + (size_t)j*DD + qc);
        } else {
            int cc = idx>>6, qn = (idx&63)<<2;
            rb[l] = *reinterpret_cast<const float4*>(Wg + (size_t)cc*DD + qn);
        }
    }
    #pragma unroll
    for(int l=0;l<8;l++){
        int idx = tid + l*256;
        uint32_t o;
        if(TB){ int j = idx>>3, qc = (idx&7)<<2;  o = (uint32_t)(j*36 + qc); }
        else  { int cc = idx>>6, qn = (idx&63)<<2; o = (uint32_t)(cc*264 + qn); }
        *reinterpret_cast<float4*>(Ws + o) = rb[l];
    }
    __syncthreads();

    #pragma unroll 1
    for(int p=0;p<8;p++){
        if(p<7){
            #pragma unroll
            for(int l=0;l<8;l++){
                int idx = tid + l*256;
                if(TB){
                    int j = idx>>3, qc = (idx&7)<<2;
                    rb[l] = *reinterpret_cast<const float4*>(Wg + (size_t)j*DD + (p+1)*32 + qc);
                } else {
                    int cc = idx>>6, qn = (idx&63)<<2;
                    rb[l] = *reinterpret_cast<const float4*>(Wg + (size_t)((p+1)*32+cc)*DD + qn);
                }
            }
        }
        const float* Wp = Ws + (p&1)*WPLANE;
        #pragma unroll
        for(int ks=0;ks<4;ks++){
            const int kk = p*32 + ks*8;
            uint32_t ah[4], al[4];
            const float* A0 = Ah + g*SA + kk + tig;
            const float* A1 = Al + g*SA + kk + tig;
            ah[0] = __float_as_uint(A0[0]);
            ah[1] = __float_as_uint(A0[8*SA]);
            ah[2] = __float_as_uint(A0[4]);
            ah[3] = __float_as_uint(A0[8*SA+4]);
            al[0] = __float_as_uint(A1[0]);
            al[1] = __float_as_uint(A1[8*SA]);
            al[2] = __float_as_uint(A1[4]);
            al[3] = __float_as_uint(A1[8*SA+4]);
            #pragma unroll
            for(int t=0;t<4;t++){
                const int jn = w*32 + t*8 + g;
                float w0, w1;
                if(TB){
                    const float* P = Wp + jn*36 + ks*8 + tig;
                    w0 = P[0]; w1 = P[4];
                } else {
                    const float* P = Wp + (ks*8+tig)*264 + jn;
                    w0 = P[0]; w1 = P[4*264];
                }
                float h0 = tf32hi(w0), h1 = tf32hi(w1);
                uint32_t bh0 = __float_as_uint(h0), bh1 = __float_as_uint(h1);
                uint32_t bl0 = __float_as_uint(w0 - h0), bl1 = __float_as_uint(w1 - h1);
                mma8(acc[t], ah, bh0, bh1);
                mma8(acc[t], al, bh0, bh1);
                mma8(acc[t], ah, bl0, bl1);
            }
        }
        if(p<7){
            float* dst = Ws + ((p+1)&1)*WPLANE;
            #pragma unroll
            for(int l=0;l<8;l++){
                int idx = tid + l*256;
                uint32_t o;
                if(TB){ int j = idx>>3, qc = (idx&7)<<2;  o = (uint32_t)(j*36 + qc); }
                else  { int cc = idx>>6, qn = (idx&63)<<2; o = (uint32_t)(cc*264 + qn); }
                *reinterpret_cast<float4*>(dst + o) = rb[l];
            }
        }
        __syncthreads();
    }
}

// ---------------- K0 ----------------
__global__ void k0_init(const float* __restrict__ k1w, const float* __restrict__ k2w,
                        const float* __restrict__ v1w, const float* __restrict__ v2w,
                        const float* __restrict__ q1w, const float* __restrict__ q2w,
                        const float* __restrict__ e1w, const float* __restrict__ e2w,
                        const float* __restrict__ esw, const float* __restrict__ a1w,
                        const float* __restrict__ a2w, const float* __restrict__ asw,
                        const float* __restrict__ m1w, const float* __restrict__ m2w){
    const int gid = blockIdx.x*blockDim.x + threadIdx.x;
    const int m = blockIdx.y;
    if(m<4){
        const float* src = (m==0)?k1w:(m==1)?v1w:(m==2)?q1w:m1w;
        float v = src[gid];
        #pragma unroll
        for(int b=0;b<BB;b++) S_w1f[m][b][gid] = v;
    } else if(m<10){
        const int s = m-4;
        const float* src = (s==0)?k2w:(s==1)?v2w:(s==2)?q2w:(s==3)?e2w:(s==4)?a2w:m2w;
        float v = src[gid];
        #pragma unroll
        for(int b=0;b<BB;b++) S_w2[s][b][gid] = v;
    } else {
        if(gid < DD){
            #pragma unroll
            for(int b=0;b<BB;b++){
                S_w1v[0][b][gid] = e1w[gid];
                S_w1v[1][b][gid] = a1w[gid];
                S_wsk[0][b][gid] = esw[gid];
                S_wsk[1][b][gid] = asw[gid];
            }
        }
    }
}

// ---------------- K1 (R7 SIMT, grid 128 x 256thr) ----------------
__global__ void __launch_bounds__(256) k1_forward(const float* __restrict__ x, int chunk){
    extern __shared__ float sm[];
    float* Xs  = sm;
    float* Hs  = sm + XTILE;
    float* Bt  = sm + 2*XTILE;
    float* Red = sm + 2*XTILE + BT2;
    const int tid = threadIdx.x, tx = tid&31;
    const int rw = (tid>>5)&3, jh = tid>>7;
    const int bx = blockIdx.x;
    const int th = bx&3, gg = (bx>>2)&3, b = bx>>4;
    const int tok0 = chunk*CHK + th*16;

    load_tile16(Xs, x + ((size_t)b*TLEN + tok0)*DD);

    u64 acc[4][4];
    if(gg < 3){
        gemmTB(Xs, S_w2[gg][b], Bt, acc);
        __syncthreads();
        #pragma unroll
        for(int r=0;r<4;r++)
            #pragma unroll
            for(int jj=0;jj<4;jj++)
                Hs[(rw*4+r)*SA + jh*128 + tx + 32*jj] = geluf(red2(acc[r][jj]));
        gemmTB(Hs, S_w1f[gg][b], Bt, acc);

        float out[4][4];
        #pragma unroll
        for(int r=0;r<4;r++){
            const int r2 = rw*4+r;
            float s = 0.f;
            #pragma unroll
            for(int jj=0;jj<4;jj++){
                const int col = jh*128 + tx + 32*jj;
                float o = Xs[r2*SA + col] + red2(acc[r][jj]);
                out[r][jj] = o;
                s += (gg==1)? o : o*o;
            }
            s = warp_sum(s);
            if(tx==0) Red[r2*2 + jh] = s;
        }
        __syncthreads();
        if(gg==1){
            #pragma unroll
            for(int r=0;r<4;r++){
                const int r2 = rw*4+r, row = th*16 + r2;
                #pragma unroll
                for(int jj=0;jj<4;jj++)
                    SC_v[b][row*DD + jh*128 + tx + 32*jj] = out[r][jj];
                if(jh==0 && tx==0) SC_vsum[b][row] = Red[r2*2] + Red[r2*2+1];
            }
        } else {
            float* dst = (gg==0)? SC_k[b] : SC_q[b];
            #pragma unroll
            for(int r=0;r<4;r++){
                const int r2 = rw*4+r, row = th*16 + r2;
                float inv = 1.f / fmaxf(sqrtf(Red[r2*2] + Red[r2*2+1]), 1e-6f);
                #pragma unroll
                for(int jj=0;jj<4;jj++)
                    dst[row*DD + jh*128 + tx + 32*jj] = out[r][jj]*inv;
            }
        }
    } else {
        #pragma unroll 1
        for(int si=0;si<2;si++){
            gemmTB(Xs, S_w2[3+si][b], Bt, acc);
            const float* wsk = S_wsk[si][b];
            const float* w1v = S_w1v[si][b];
            #pragma unroll
            for(int r=0;r<4;r++){
                const int r2 = rw*4+r;
                float p = 0.f;
                #pragma unroll
                for(int jj=0;jj<4;jj++){
                    const int col = jh*128 + tx + 32*jj;
                    float h = geluf(red2(acc[r][jj]));
                    p += Xs[r2*SA + col]*wsk[col] + h*w1v[col];
                }
                p = warp_sum(p);
                if(tx==0) Red[r2*2 + jh] = p;
            }
            __syncthreads();
            if(jh==0 && tx==0){
                #pragma unroll
                for(int r=0;r<4;r++){
                    const int r2 = rw*4+r, row = th*16 + r2;
                    float pt = Red[r2*2] + Red[r2*2+1];
                    if(si==0){ float sp = (pt>20.f)? pt : log1pf(expf(pt)); SC_eta[b][row] = sp*0.001f; }
                    else       SC_alpha[b][row] = 1.f/(1.f+expf(-pt));
                }
            }
            __syncthreads();
        }
    }
}

// ---------------- K2: mma heavy (128) + SIMT small (64) + SIMT o (32) ----------------
__global__ void __launch_bounds__(256) k2_token(float* __restrict__ dout, int chunk){
    extern __shared__ float sm[];
    const int tid = threadIdx.x, tx = tid&31;
    const int bx = blockIdx.x;

    if(bx < 128){
        float* Ah = sm;
        float* Al = sm + OF_AL;
        float* Ws = sm + OF_WS;
        const int th = bx&3, f = (bx>>2)&3, b = bx>>4;
        const int s = (f==3)? 5 : f;
        const int w = tid>>5, g = tx>>2, tig = tx&3;
        const float* Kg = SC_k[b] + th*16*DD;
        const float* Vg = SC_v[b] + th*16*DD;

        // load + split K tile into hi/lo activation planes
        #pragma unroll
        for(int l=0;l<4;l++){
            int idx = tid + l*256;
            int r = idx>>6, qc = (idx&63)<<2;
            float4 v = *reinterpret_cast<const float4*>(Kg + (size_t)r*DD + qc);
            float4 h, lo;
            h.x = tf32hi(v.x); lo.x = v.x - h.x;
            h.y = tf32hi(v.y); lo.y = v.y - h.y;
            h.z = tf32hi(v.z); lo.z = v.z - h.z;
            h.w = tf32hi(v.w); lo.w = v.w - h.w;
            *reinterpret_cast<float4*>(Ah + r*SA + qc) = h;
            *reinterpret_cast<float4*>(Al + r*SA + qc) = lo;
        }

        float acc[4][4], dz[4][4];
        // gemm1: z = K @ W2^T
        mgemm<1>(Ah, Al, S_w2[s][b], Ws, acc);
        #pragma unroll
        for(int t=0;t<4;t++)
            #pragma unroll
            for(int e=0;e<4;e++){
                const int r = g + ((e>>1)<<3);
                const int j = w*32 + t*8 + 2*tig + (e&1);
                float z = acc[t][e];
                float h = geluf(z);
                dz[t][e] = dgeluf(z);
                SC_h2[s][b][(th*16 + r)*DD + j] = h;
                float hh = tf32hi(h);
                Ah[r*SA + j] = hh;
                Al[r*SA + j] = h - hh;
            }
        // gemm2: fval = H @ W1^T ; g = 2(k + f - v)
        mgemm<1>(Ah, Al, S_w1f[f][b], Ws, acc);
        #pragma unroll
        for(int t=0;t<4;t++)
            #pragma unroll
            for(int e=0;e<4;e++){
                const int r = g + ((e>>1)<<3);
                const int j = w*32 + t*8 + 2*tig + (e&1);
                float gg = 2.f*(Kg[(size_t)r*DD + j] + acc[t][e] - Vg[(size_t)r*DD + j]);
                SC_g[f][b][(th*16 + r)*DD + j] = gg;
                float gh = tf32hi(gg);
                Ah[r*SA + j] = gh;
                Al[r*SA + j] = gg - gh;
            }
        // gemm3: pre = (G @ W1) * dgelu(z)
        mgemm<0>(Ah, Al, S_w1f[f][b], Ws, acc);
        #pragma unroll
        for(int t=0;t<4;t++)
            #pragma unroll
            for(int e=0;e<4;e++){
                const int r = g + ((e>>1)<<3);
                const int j = w*32 + t*8 + 2*tig + (e&1);
                SC_pre[s][b][(th*16 + r)*DD + j] = acc[t][e]*dz[t][e];
            }
    } else if(bx < 192){
        const int rw = (tid>>5)&3, jh = tid>>7;
        float* Ks  = sm;
        float* Bt  = sm + XTILE;
        float* Red = sm + XTILE + BT2;
        const int i = bx-128, th = i&3, si = (i>>2)&1, b = i>>3;
        const int s = 3+si;

        load_tile16(Ks, SC_k[b] + th*16*DD);
        u64 acc[4][4];
        gemmTB(Ks, S_w2[s][b], Bt, acc);
        const float* wsk = S_wsk[si][b];
        const float* w1v = S_w1v[si][b];
        float zr[4][4];
        #pragma unroll
        for(int r=0;r<4;r++){
            const int r2 = rw*4+r;
            float p = 0.f;
            #pragma unroll
            for(int jj=0;jj<4;jj++){
                const int col = jh*128 + tx + 32*jj;
                float z = red2(acc[r][jj]); zr[r][jj] = z;
                float h = geluf(z);
                SC_h2[s][b][(th*16 + r2)*DD + col] = h;
                p += Ks[r2*SA + col]*wsk[col] + h*w1v[col];
            }
            p = warp_sum(p);
            if(tx==0) Red[r2*2 + jh] = p;
        }
        __syncthreads();
        #pragma unroll
        for(int r=0;r<4;r++){
            const int r2 = rw*4+r, row = th*16 + r2;
            float pt = Red[r2*2] + Red[r2*2+1];
            float g = 2.f*(256.f*pt - SC_vsum[b][row]);
            if(jh==0 && tx==0) SC_gs[si][b][row] = g;
            #pragma unroll
            for(int jj=0;jj<4;jj++){
                const int col = jh*128 + tx + 32*jj;
                SC_pre[s][b][row*DD + col] = g * w1v[col] * dgeluf(zr[r][jj]);
            }
        }
    } else {
        const int rw = (tid>>5)&3, jh = tid>>7;
        float* Qs = sm;
        float* Hs = sm + XTILE;
        float* Bt = sm + 2*XTILE;
        const int i = bx-192, th = i&3, b = i>>2;

        load_tile16(Qs, SC_q[b] + th*16*DD);
        u64 acc[4][4];
        gemmTB(Qs, S_w2[5][b], Bt, acc);
        __syncthreads();
        #pragma unroll
        for(int r=0;r<4;r++)
            #pragma unroll
            for(int jj=0;jj<4;jj++)
                Hs[(rw*4+r)*SA + jh*128 + tx + 32*jj] = geluf(red2(acc[r][jj]));
        gemmTB(Hs, S_w1f[3][b], Bt, acc);
        #pragma unroll
        for(int r=0;r<4;r++)
            #pragma unroll
            for(int jj=0;jj<4;jj++){
                const int r2 = rw*4+r, col = jh*128 + tx + 32*jj;
                size_t off = ((size_t)b*TLEN + (size_t)chunk*CHK + th*16 + r2)*DD + col;
                dout[off] = Qs[r2*SA + col] + red2(acc[r][jj]);
            }
        if(th==0 && tid==0){
            float p = 1.f;
            #pragma unroll
            for(int t=0;t<CHK;t++) p *= SC_alpha[b][t];
            SC_abar[b] = p;
        }
    }
}

// ---------------- K3: IN-PLACE weight updates (grid 656 x 256thr) [R7 exact] --------
__global__ void __launch_bounds__(256) k3_weights(){
    extern __shared__ float sm[];
    float* Ges = sm;
    float* Bs  = sm + 64*66;
    const int tid = threadIdx.x, wid = tid>>5, tx = tid&31;
    const int bx = blockIdx.x;

    if(bx < 640){
        int b, ot, ch;
        const float *A, *Bsrc; float* W;
        if(bx < 512){
            b = bx>>6; int r = bx&63;
            int f = r>>4, m = (r>>3)&1; ot = (r>>1)&3; ch = r&1;
            int s = (f==3)? 5 : f;
            if(m==0){ A = SC_g[f][b];   Bsrc = SC_h2[s][b]; W = S_w1f[f][b]; }
            else    { A = SC_pre[s][b]; Bsrc = SC_k[b];     W = S_w2[s][b];  }
        } else {
            int i = bx-512; b = i>>4; int r = i&15;
            int si = r>>3; ot = (r>>1)&3; ch = r&1;
            A = SC_pre[3+si][b]; Bsrc = SC_k[b]; W = S_w2[3+si][b];
        }
        const float abar = SC_abar[b];
        const float* eta = SC_eta[b];

        #pragma unroll
        for(int l=0;l<8;l++){
            int idx = tid + l*256;
            int t = idx>>5, qc = (idx&31)<<2;
            *reinterpret_cast<float4*>(Bs + t*132 + qc) =
                *reinterpret_cast<const float4*>(Bsrc + t*DD + ch*128 + qc);
        }
        #pragma unroll
        for(int l=0;l<4;l++){
            int idx = tid + l*256;
            int t = idx>>4, oq = (idx&15)<<2;
            float e = eta[t];
            float4 v = *reinterpret_cast<const float4*>(A + t*DD + ot*64 + oq);
            float2* p = reinterpret_cast<float2*>(Ges + t*66 + oq);
            p[0] = make_float2(v.x*e, v.y*e);
            p[1] = make_float2(v.z*e, v.w*e);
        }
        __syncthreads();

        u64 acc[4][4];
        #pragma unroll
        for(int rp=0;rp<4;rp++)
            #pragma unroll
            for(int j=0;j<4;j++) acc[rp][j] = 0ull;

        #pragma unroll 4
        for(int t=0;t<64;t++){
            u64 a[4];
            #pragma unroll
            for(int rp=0;rp<4;rp++)
                a[rp] = *reinterpret_cast<const u64*>(Ges + t*66 + wid*8 + 2*rp);
            float4 bv = *reinterpret_cast<const float4*>(Bs + t*132 + tx*4);
            u64 b0 = pk2(bv.x,bv.x), b1 = pk2(bv.y,bv.y), b2 = pk2(bv.z,bv.z), b3 = pk2(bv.w,bv.w);
            #pragma unroll
            for(int rp=0;rp<4;rp++){
                fmaX2(acc[rp][0], a[rp], b0);
                fmaX2(acc[rp][1], a[rp], b1);
                fmaX2(acc[rp][2], a[rp], b2);
                fmaX2(acc[rp][3], a[rp], b3);
            }
        }
        #pragma unroll
        for(int rp=0;rp<4;rp++){
            const int row0 = ot*64 + wid*8 + 2*rp;
            size_t off0 = (size_t)row0*DD + ch*128 + tx*4;
            float4 w0 = *reinterpret_cast<const float4*>(W + off0);
            float4 w1 = *reinterpret_cast<const float4*>(W + off0 + DD);
            float2 c0 = up2(acc[rp][0]), c1 = up2(acc[rp][1]);
            float2 c2 = up2(acc[rp][2]), c3 = up2(acc[rp][3]);
            *reinterpret_cast<float4*>(W + off0) =
                make_float4(abar*w0.x - c0.x, abar*w0.y - c1.x,
                            abar*w0.z - c2.x, abar*w0.w - c3.x);
            *reinterpret_cast<float4*>(W + off0 + DD) =
                make_float4(abar*w1.x - c0.y, abar*w1.y - c1.y,
                            abar*w1.z - c2.y, abar*w1.w - c3.y);
        }
    } else {
        const int i = bx-640, b = i>>1, si = i&1, s = 3+si;
        const float abar = SC_abar[b];
        const int j = tid;
        float aA = 0.f, aB = 0.f;
        #pragma unroll 4
        for(int t=0;t<CHK;t++){
            float ge = SC_gs[si][b][t]*SC_eta[b][t];
            aA += ge * SC_h2[s][b][t*DD + j];
            aB += ge * SC_k[b][t*DD + j];
        }
        S_w1v[si][b][j] = abar*S_w1v[si][b][j] - aA;
        S_wsk[si][b][j] = abar*S_wsk[si][b][j] - aB;
    }
}

// ---------------- launch ----------------
#define SMEM1 ((2*XTILE + BT2 + 32)*4)       // 103168 B
#define SMEM2 (SM2F*4)                        // 107008 B
#define SMEM3 ((64*66 + 64*132)*4)           //  50688 B

extern "C" void kernel_launch(void* const* d_in, const int* in_sizes, int n_in,
                              void* d_out, int out_size){
    (void)in_sizes; (void)n_in; (void)out_size;
    const float* x   = (const float*)d_in[0];
    const float* k1w = (const float*)d_in[1];
    const float* k2w = (const float*)d_in[2];
    const float* v1w = (const float*)d_in[3];
    const float* v2w = (const float*)d_in[4];
    const float* q1w = (const float*)d_in[5];
    const float* q2w = (const float*)d_in[6];
    const float* e1w = (const float*)d_in[7];
    const float* e2w = (const float*)d_in[8];
    const float* esw = (const float*)d_in[9];
    const float* a1w = (const float*)d_in[10];
    const float* a2w = (const float*)d_in[11];
    const float* asw = (const float*)d_in[12];
    const float* m1w = (const float*)d_in[13];
    const float* m2w = (const float*)d_in[14];
    float* out = (float*)d_out;

    cudaFuncSetAttribute(k1_forward, cudaFuncAttributeMaxDynamicSharedMemorySize, SMEM1);
    cudaFuncSetAttribute(k2_token,   cudaFuncAttributeMaxDynamicSharedMemorySize, SMEM2);
    cudaFuncSetAttribute(k3_weights, cudaFuncAttributeMaxDynamicSharedMemorySize, SMEM3);

    k0_init<<<dim3(DD*DD/256, 11), 256>>>(k1w,k2w,v1w,v2w,q1w,q2w,e1w,e2w,esw,a1w,a2w,asw,m1w,m2w);

    for(int c=0;c<NC;c++){
        k1_forward<<<128, 256, SMEM1>>>(x, c);
        k2_token  <<<224, 256, SMEM2>>>(out, c);
        k3_weights<<<656, 256, SMEM3>>>();
    }
}